// round 10
// baseline (speedup 1.0000x reference)
#include <cuda_runtime.h>
#include <cuda_bf16.h>
#include <cstdint>

// ---------------------------------------------------------------------------
// APPNP dense surrogate, N=8192, F=MLP=512, C=256, 10 power iters, alpha=0.1.
// sm_103 (non-'a') target: tcgen05 unavailable -> legacy mma.sync only.
//   - MLP / projection GEMMs: bf16 mma.sync.m16n8k16 (proven R8 kernel).
//   - 10 power iterations (65% of FLOPs): fp8 e4m3 mma.sync.m16n8k32 at
//     (expected) 2x rate. A scaled x4096 into e4m3, Z iterates scaled x128;
//     APPNP mix + outputs stay fp32/bf16 in the epilogue.
// Transposed-activation layout: every GEMM's B operand is K-major [N,K].
// ---------------------------------------------------------------------------

#define NN   8192
#define FD   512
#define CD   256
#define ALPHA 0.1f
#define SA   4096.0f     // A fp8 scale
#define SZ   128.0f      // Z fp8 scale

#define BM 128
#define BN 128
#define BK 32
#define ASTR 40                                  // bf16 smem stride (elems)
#define STAGES 4
#define STAGE_ELS (BM * ASTR)
#define SMEM_BYTES (STAGES * 2 * STAGE_ELS * 2)  // 81920 B (bf16 gemm)

// fp8 gemm tiling: BK=64 bytes, row stride 80 B (conflict-free frag loads)
#define F8_STR 80
#define F8_TILE (128 * F8_STR)                   // 10240 B
#define F8_SMEM (STAGES * 2 * F8_TILE)           // 81920 B

// ---- scratch (static device globals; allocations forbidden) ---------------
__device__ __nv_bfloat16 g_Abf[(size_t)NN * NN];     // 128 MB
__device__ uint8_t       g_Af8[(size_t)NN * NN];     // 64 MB (A * SA, e4m3)
__device__ __nv_bfloat16 g_Fbf[(size_t)NN * FD];
__device__ __nv_bfloat16 g_W0t[FD * FD];
__device__ __nv_bfloat16 g_W1t[FD * FD];
__device__ __nv_bfloat16 g_Wot[FD * CD];
__device__ __nv_bfloat16 g_Yt[(size_t)FD * NN];
__device__ __nv_bfloat16 g_X[(size_t)NN * FD];
__device__ __nv_bfloat16 g_Z0t[(size_t)CD * NN];
__device__ __nv_bfloat16 g_Za[(size_t)CD * NN];      // bf16 power output
__device__ uint8_t       g_Zf0[(size_t)CD * NN];     // fp8 Z ring
__device__ uint8_t       g_Zfa[(size_t)CD * NN];
__device__ uint8_t       g_Zfb[(size_t)CD * NN];

__device__ __forceinline__ uint32_t sptr(const void* p) {
    return (uint32_t)__cvta_generic_to_shared(p);
}
__device__ __forceinline__ uint16_t pack_e4m3(float hi, float lo) {
    uint16_t u;
    asm("cvt.rn.satfinite.e4m3x2.f32 %0, %1, %2;" : "=h"(u) : "f"(hi), "f"(lo));
    return u;   // lo in low byte
}

// ---- converts -------------------------------------------------------------
__global__ void f32_to_bf16_kernel(const float* __restrict__ src,
                                   __nv_bfloat16* __restrict__ dst, long n8) {
    long t = (long)blockIdx.x * blockDim.x + threadIdx.x;
    if (t >= n8) return;
    long i = t * 8;
    float4 a = *(const float4*)(src + i);
    float4 b = *(const float4*)(src + i + 4);
    union { int4 v; __nv_bfloat16 h[8]; } u;
    u.h[0] = __float2bfloat16(a.x); u.h[1] = __float2bfloat16(a.y);
    u.h[2] = __float2bfloat16(a.z); u.h[3] = __float2bfloat16(a.w);
    u.h[4] = __float2bfloat16(b.x); u.h[5] = __float2bfloat16(b.y);
    u.h[6] = __float2bfloat16(b.z); u.h[7] = __float2bfloat16(b.w);
    *(int4*)(dst + i) = u.v;
}

__global__ void f32_to_fp8_kernel(const float* __restrict__ src,
                                  uint8_t* __restrict__ dst, float scale, long n8) {
    long t = (long)blockIdx.x * blockDim.x + threadIdx.x;
    if (t >= n8) return;
    long i = t * 8;
    float4 a = *(const float4*)(src + i);
    float4 b = *(const float4*)(src + i + 4);
    ushort4 o;
    o.x = pack_e4m3(a.y * scale, a.x * scale);
    o.y = pack_e4m3(a.w * scale, a.z * scale);
    o.z = pack_e4m3(b.y * scale, b.x * scale);
    o.w = pack_e4m3(b.w * scale, b.z * scale);
    *(ushort4*)(dst + i) = o;
}

__global__ void bf16_to_fp8_kernel(const __nv_bfloat16* __restrict__ src,
                                   uint8_t* __restrict__ dst, float scale, long n8) {
    long t = (long)blockIdx.x * blockDim.x + threadIdx.x;
    if (t >= n8) return;
    long i = t * 8;
    union { int4 v; __nv_bfloat162 h[4]; } u;
    u.v = *(const int4*)(src + i);
    ushort4 o;
    o.x = pack_e4m3(__bfloat162float(u.h[0].y) * scale, __bfloat162float(u.h[0].x) * scale);
    o.y = pack_e4m3(__bfloat162float(u.h[1].y) * scale, __bfloat162float(u.h[1].x) * scale);
    o.z = pack_e4m3(__bfloat162float(u.h[2].y) * scale, __bfloat162float(u.h[2].x) * scale);
    o.w = pack_e4m3(__bfloat162float(u.h[3].y) * scale, __bfloat162float(u.h[3].x) * scale);
    *(ushort4*)(dst + i) = o;
}

// ---- merged W transposing convert (one launch so ncu -s5 lands on a GEMM) -
__global__ void wcvt_T_kernel(const float* __restrict__ W0,
                              const float* __restrict__ W1,
                              const float* __restrict__ Wo,
                              __nv_bfloat16* __restrict__ W0t,
                              __nv_bfloat16* __restrict__ W1t,
                              __nv_bfloat16* __restrict__ Wot) {
    __shared__ float t[32][33];
    const float* src; __nv_bfloat16* dst; int C;
    if (blockIdx.z == 0)      { src = W0; dst = W0t; C = FD; }
    else if (blockIdx.z == 1) { src = W1; dst = W1t; C = FD; }
    else                      { src = Wo; dst = Wot; C = CD; }
    int c0 = blockIdx.x * 32, r0 = blockIdx.y * 32;
    if (c0 >= C) return;
    int tx = threadIdx.x, ty = threadIdx.y;   // (32, 8)
#pragma unroll
    for (int j = 0; j < 32; j += 8)
        t[ty + j][tx] = src[(size_t)(r0 + ty + j) * C + c0 + tx];
    __syncthreads();
#pragma unroll
    for (int j = 0; j < 32; j += 8)
        dst[(size_t)(c0 + ty + j) * FD + r0 + tx] = __float2bfloat16(t[tx][ty + j]);
}

// ---- bf16 GEMM (unchanged from R8): C = epi(Aop[M,K] @ B), Bt[N,K] --------
// MODE 0: acc + bias[row]   MODE 1: relu(acc)
template <int MODE>
__global__ void __launch_bounds__(256)
gemm_bf16_kernel(const __nv_bfloat16* __restrict__ Aop,
                 const __nv_bfloat16* __restrict__ Btp,
                 __nv_bfloat16* __restrict__ C,
                 int M, int N, int K,
                 const float* __restrict__ bias) {
    extern __shared__ __nv_bfloat16 dsm[];
    __nv_bfloat16* As = dsm;
    __nv_bfloat16* Bs = dsm + STAGES * STAGE_ELS;

    const int tid  = threadIdx.x;
    const int lane = tid & 31;
    const int warp = tid >> 5;
    const int wm = (warp & 3) * 32;
    const int wn = (warp >> 2) * 64;
    const int bm0 = blockIdx.y * BM;
    const int bn0 = blockIdx.x * BN;
    const int nIter = K / BK;

    auto load_stage = [&](int st, int kiter) {
        const int k0 = kiter * BK;
        __nv_bfloat16* Asb = As + st * STAGE_ELS;
        __nv_bfloat16* Bsb = Bs + st * STAGE_ELS;
#pragma unroll
        for (int r = 0; r < 2; r++) {
            int idx = tid + r * 256;
            int row = idx >> 2;
            int c8  = (idx & 3) * 8;
            uint32_t da = sptr(Asb + row * ASTR + c8);
            const void* ga = Aop + (size_t)(bm0 + row) * K + k0 + c8;
            asm volatile("cp.async.cg.shared.global [%0], [%1], 16;\n" :: "r"(da), "l"(ga));
            uint32_t db = sptr(Bsb + row * ASTR + c8);
            const void* gb = Btp + (size_t)(bn0 + row) * K + k0 + c8;
            asm volatile("cp.async.cg.shared.global [%0], [%1], 16;\n" :: "r"(db), "l"(gb));
        }
        asm volatile("cp.async.commit_group;\n");
    };

    float acc[2][8][4];
#pragma unroll
    for (int i = 0; i < 2; i++)
#pragma unroll
        for (int j = 0; j < 8; j++)
#pragma unroll
            for (int k = 0; k < 4; k++) acc[i][j][k] = 0.f;

    const int arow = lane >> 2;
    const int acol = (lane & 3) * 2;

#pragma unroll
    for (int s = 0; s < STAGES - 1; s++) load_stage(s, s);

    for (int it = 0; it < nIter; it++) {
        asm volatile("cp.async.wait_group %0;\n" :: "n"(STAGES - 2));
        __syncthreads();

        int nxt = it + STAGES - 1;
        if (nxt < nIter) load_stage(nxt % STAGES, nxt);
        else asm volatile("cp.async.commit_group;\n");

        const __nv_bfloat16* Asb = As + (it % STAGES) * STAGE_ELS;
        const __nv_bfloat16* Bsb = Bs + (it % STAGES) * STAGE_ELS;

#pragma unroll
        for (int kk = 0; kk < BK; kk += 16) {
            uint32_t af[2][4], bf[8][2];
#pragma unroll
            for (int mi = 0; mi < 2; mi++) {
                const __nv_bfloat16* p = &Asb[(wm + mi * 16 + arow) * ASTR + kk + acol];
                af[mi][0] = *(const uint32_t*)(p);
                af[mi][1] = *(const uint32_t*)(p + 8 * ASTR);
                af[mi][2] = *(const uint32_t*)(p + 8);
                af[mi][3] = *(const uint32_t*)(p + 8 * ASTR + 8);
            }
#pragma unroll
            for (int nj = 0; nj < 8; nj++) {
                const __nv_bfloat16* p = &Bsb[(wn + nj * 8 + arow) * ASTR + kk + acol];
                bf[nj][0] = *(const uint32_t*)(p);
                bf[nj][1] = *(const uint32_t*)(p + 8);
            }
#pragma unroll
            for (int mi = 0; mi < 2; mi++)
#pragma unroll
                for (int nj = 0; nj < 8; nj++) {
                    asm volatile(
                        "mma.sync.aligned.m16n8k16.row.col.f32.bf16.bf16.f32 "
                        "{%0,%1,%2,%3}, {%4,%5,%6,%7}, {%8,%9}, {%0,%1,%2,%3};\n"
                        : "+f"(acc[mi][nj][0]), "+f"(acc[mi][nj][1]),
                          "+f"(acc[mi][nj][2]), "+f"(acc[mi][nj][3])
                        : "r"(af[mi][0]), "r"(af[mi][1]), "r"(af[mi][2]), "r"(af[mi][3]),
                          "r"(bf[nj][0]), "r"(bf[nj][1]));
                }
        }
    }

#pragma unroll
    for (int mi = 0; mi < 2; mi++) {
#pragma unroll
        for (int nj = 0; nj < 8; nj++) {
            int row0 = bm0 + wm + mi * 16 + arow;
            int col0 = bn0 + wn + nj * 8 + acol;
#pragma unroll
            for (int h = 0; h < 2; h++) {
                int row = row0 + h * 8;
                float v0 = acc[mi][nj][2 * h + 0];
                float v1 = acc[mi][nj][2 * h + 1];
                if (MODE == 0) { float b = bias[row]; v0 += b; v1 += b; }
                if (MODE == 1) { v0 = fmaxf(v0, 0.f); v1 = fmaxf(v1, 0.f); }
                *(__nv_bfloat162*)(C + (size_t)row * N + col0) = __floats2bfloat162_rn(v0, v1);
            }
        }
    }
}

// ---- fp8 power-iteration GEMM ---------------------------------------------
// Zt_new[c,n] = 0.9/(SA*SZ) * sum_k Zf8[c,k]*Af8[n,k] + 0.1*Z0[c,n]
// Writes bf16 (for softmax) AND fp8*SZ (next iteration input).
__global__ void __launch_bounds__(256)
gemm_fp8_pow(const uint8_t* __restrict__ Zin,
             const uint8_t* __restrict__ Aop8,
             __nv_bfloat16* __restrict__ Cbf,
             uint8_t* __restrict__ Cf8,
             const __nv_bfloat16* __restrict__ Z0,
             int N, int K) {
    extern __shared__ uint8_t dyn8[];
    uint8_t* As = dyn8;
    uint8_t* Bs = dyn8 + STAGES * F8_TILE;

    const int tid  = threadIdx.x;
    const int lane = tid & 31;
    const int warp = tid >> 5;
    const int wm = (warp & 3) * 32;
    const int wn = (warp >> 2) * 64;
    const int bm0 = blockIdx.y * BM;
    const int bn0 = blockIdx.x * BN;
    const int nIter = K / 64;

    auto load_stage = [&](int st, int kiter) {
        const int k0 = kiter * 64;
        uint8_t* Asb = As + st * F8_TILE;
        uint8_t* Bsb = Bs + st * F8_TILE;
#pragma unroll
        for (int r = 0; r < 2; r++) {
            int idx = tid + r * 256;
            int row = idx >> 2;
            int c16 = (idx & 3) * 16;
            uint32_t da = sptr(Asb + row * F8_STR + c16);
            const void* ga = Zin + (size_t)(bm0 + row) * K + k0 + c16;
            asm volatile("cp.async.cg.shared.global [%0], [%1], 16;\n" :: "r"(da), "l"(ga));
            uint32_t db = sptr(Bsb + row * F8_STR + c16);
            const void* gb = Aop8 + (size_t)(bn0 + row) * K + k0 + c16;
            asm volatile("cp.async.cg.shared.global [%0], [%1], 16;\n" :: "r"(db), "l"(gb));
        }
        asm volatile("cp.async.commit_group;\n");
    };

    float acc[2][8][4];
#pragma unroll
    for (int i = 0; i < 2; i++)
#pragma unroll
        for (int j = 0; j < 8; j++)
#pragma unroll
            for (int k = 0; k < 4; k++) acc[i][j][k] = 0.f;

    const int arow  = lane >> 2;
    const int acol4 = (lane & 3) * 4;

#pragma unroll
    for (int s = 0; s < STAGES - 1; s++) load_stage(s, s);

    for (int it = 0; it < nIter; it++) {
        asm volatile("cp.async.wait_group %0;\n" :: "n"(STAGES - 2));
        __syncthreads();

        int nxt = it + STAGES - 1;
        if (nxt < nIter) load_stage(nxt % STAGES, nxt);
        else asm volatile("cp.async.commit_group;\n");

        const uint8_t* Asb = As + (it % STAGES) * F8_TILE;
        const uint8_t* Bsb = Bs + (it % STAGES) * F8_TILE;

#pragma unroll
        for (int kk = 0; kk < 64; kk += 32) {
            uint32_t af[2][4], bf8[8][2];
#pragma unroll
            for (int mi = 0; mi < 2; mi++) {
                const uint8_t* p = Asb + (wm + mi * 16 + arow) * F8_STR + kk + acol4;
                af[mi][0] = *(const uint32_t*)(p);
                af[mi][1] = *(const uint32_t*)(p + 8 * F8_STR);
                af[mi][2] = *(const uint32_t*)(p + 16);
                af[mi][3] = *(const uint32_t*)(p + 8 * F8_STR + 16);
            }
#pragma unroll
            for (int nj = 0; nj < 8; nj++) {
                const uint8_t* p = Bsb + (wn + nj * 8 + arow) * F8_STR + kk + acol4;
                bf8[nj][0] = *(const uint32_t*)(p);
                bf8[nj][1] = *(const uint32_t*)(p + 16);
            }
#pragma unroll
            for (int mi = 0; mi < 2; mi++)
#pragma unroll
                for (int nj = 0; nj < 8; nj++) {
                    asm volatile(
                        "mma.sync.aligned.m16n8k32.row.col.f32.e4m3.e4m3.f32 "
                        "{%0,%1,%2,%3}, {%4,%5,%6,%7}, {%8,%9}, {%0,%1,%2,%3};\n"
                        : "+f"(acc[mi][nj][0]), "+f"(acc[mi][nj][1]),
                          "+f"(acc[mi][nj][2]), "+f"(acc[mi][nj][3])
                        : "r"(af[mi][0]), "r"(af[mi][1]), "r"(af[mi][2]), "r"(af[mi][3]),
                          "r"(bf8[nj][0]), "r"(bf8[nj][1]));
                }
        }
    }

    const float S09 = (1.f - ALPHA) / (SA * SZ);
#pragma unroll
    for (int mi = 0; mi < 2; mi++) {
#pragma unroll
        for (int nj = 0; nj < 8; nj++) {
            int row0 = bm0 + wm + mi * 16 + arow;
            int col0 = bn0 + wn + nj * 8 + acol4 / 2;   // C frag: cols 2*(lane&3)
            // NOTE: for 8-bit mma the C layout matches f16: cols = (lane&3)*2
#pragma unroll
            for (int h = 0; h < 2; h++) {
                int row = row0 + h * 8;
                int col = bn0 + wn + nj * 8 + (lane & 3) * 2;
                __nv_bfloat162 z = *(const __nv_bfloat162*)(Z0 + (size_t)row * N + col);
                float v0 = acc[mi][nj][2 * h + 0] * S09 + ALPHA * __bfloat162float(z.x);
                float v1 = acc[mi][nj][2 * h + 1] * S09 + ALPHA * __bfloat162float(z.y);
                *(__nv_bfloat162*)(Cbf + (size_t)row * N + col) = __floats2bfloat162_rn(v0, v1);
                *(uint16_t*)(Cf8 + (size_t)row * N + col) = pack_e4m3(v1 * SZ, v0 * SZ);
            }
            (void)col0;
        }
    }
}

// ---- column softmax of Zt[256, 8192] -> out[8192, 256] fp32 ---------------
__global__ void softmax_T_kernel(const __nv_bfloat16* __restrict__ Zt,
                                 float* __restrict__ out) {
    __shared__ float tile[2][32][33];
    int warp = threadIdx.x >> 5, lane = threadIdx.x & 31;
    int n0 = blockIdx.x * 64 + warp * 32;
    int n = n0 + lane;

    float mx = -1e30f;
#pragma unroll 8
    for (int c = 0; c < CD; c++)
        mx = fmaxf(mx, __bfloat162float(Zt[(size_t)c * NN + n]));
    float s = 0.f;
#pragma unroll 8
    for (int c = 0; c < CD; c++)
        s += __expf(__bfloat162float(Zt[(size_t)c * NN + n]) - mx);
    float inv = 1.f / s;

    for (int c0 = 0; c0 < CD; c0 += 32) {
#pragma unroll
        for (int cc = 0; cc < 32; cc++)
            tile[warp][cc][lane] =
                __expf(__bfloat162float(Zt[(size_t)(c0 + cc) * NN + n]) - mx) * inv;
        __syncwarp();
#pragma unroll
        for (int i = 0; i < 32; i++)
            out[(size_t)(n0 + i) * CD + c0 + lane] = tile[warp][lane][i];
        __syncwarp();
    }
}

// ---------------------------------------------------------------------------
extern "C" void kernel_launch(void* const* d_in, const int* in_sizes, int n_in,
                              void* d_out, int out_size) {
    const float* features = (const float*)d_in[0];
    const float* fltr     = (const float*)d_in[1];
    const float* W0       = (const float*)d_in[2];
    const float* b0       = (const float*)d_in[3];
    const float* W1       = (const float*)d_in[4];
    const float* b1       = (const float*)d_in[5];
    const float* Wo       = (const float*)d_in[6];
    const float* bo       = (const float*)d_in[7];

    void *pA, *pA8, *pF, *pW0, *pW1, *pWo, *pYt, *pX, *pZ0, *pZa, *pZf0, *pZfa, *pZfb;
    cudaGetSymbolAddress(&pA,   g_Abf);
    cudaGetSymbolAddress(&pA8,  g_Af8);
    cudaGetSymbolAddress(&pF,   g_Fbf);
    cudaGetSymbolAddress(&pW0,  g_W0t);
    cudaGetSymbolAddress(&pW1,  g_W1t);
    cudaGetSymbolAddress(&pWo,  g_Wot);
    cudaGetSymbolAddress(&pYt,  g_Yt);
    cudaGetSymbolAddress(&pX,   g_X);
    cudaGetSymbolAddress(&pZ0,  g_Z0t);
    cudaGetSymbolAddress(&pZa,  g_Za);
    cudaGetSymbolAddress(&pZf0, g_Zf0);
    cudaGetSymbolAddress(&pZfa, g_Zfa);
    cudaGetSymbolAddress(&pZfb, g_Zfb);

    __nv_bfloat16* Abf = (__nv_bfloat16*)pA;
    uint8_t*       Af8 = (uint8_t*)pA8;
    __nv_bfloat16* Fbf = (__nv_bfloat16*)pF;
    __nv_bfloat16* W0t = (__nv_bfloat16*)pW0;
    __nv_bfloat16* W1t = (__nv_bfloat16*)pW1;
    __nv_bfloat16* Wot = (__nv_bfloat16*)pWo;
    __nv_bfloat16* Yt  = (__nv_bfloat16*)pYt;
    __nv_bfloat16* Xb  = (__nv_bfloat16*)pX;
    __nv_bfloat16* Z0t = (__nv_bfloat16*)pZ0;
    __nv_bfloat16* Za  = (__nv_bfloat16*)pZa;
    uint8_t*       Zf0 = (uint8_t*)pZf0;
    uint8_t*       Zfa = (uint8_t*)pZfa;
    uint8_t*       Zfb = (uint8_t*)pZfb;

    cudaFuncSetAttribute(gemm_bf16_kernel<0>, cudaFuncAttributeMaxDynamicSharedMemorySize, SMEM_BYTES);
    cudaFuncSetAttribute(gemm_bf16_kernel<1>, cudaFuncAttributeMaxDynamicSharedMemorySize, SMEM_BYTES);
    cudaFuncSetAttribute(gemm_fp8_pow,        cudaFuncAttributeMaxDynamicSharedMemorySize, F8_SMEM);

    // 0) converts (4 launches before the GEMMs)
    {
        long n8 = (long)NN * NN / 8;
        f32_to_bf16_kernel<<<(int)((n8 + 255) / 256), 256>>>(fltr, Abf, n8);
        f32_to_fp8_kernel<<<(int)((n8 + 255) / 256), 256>>>(fltr, Af8, SA, n8);
        long f8 = (long)NN * FD / 8;
        f32_to_bf16_kernel<<<(int)((f8 + 255) / 256), 256>>>(features, Fbf, f8);
        wcvt_T_kernel<<<dim3(16, 16, 3), dim3(32, 8)>>>(W0, W1, Wo, W0t, W1t, Wot);
    }

    dim3 gridYt(NN / BN, FD / BM);   // [512, 8192]
    dim3 gridX (FD / BN, NN / BM);   // [8192, 512]
    dim3 gridZ0(NN / BN, CD / BM);   // [256, 8192]
    dim3 gridZ (NN / BN, CD / BM);   // fp8 power iters

    // 1) Yt = W0t @ Ft (+b0 row)
    gemm_bf16_kernel<0><<<gridYt, 256, SMEM_BYTES>>>(W0t, Fbf, Yt, FD, NN, FD, b0);
    // 2) X = relu(A @ Y)        <- ncu -s5 -c1 captures this launch
    gemm_bf16_kernel<1><<<gridX, 256, SMEM_BYTES>>>(Abf, Yt, Xb, NN, FD, NN, nullptr);
    // 3) Yt = W1t @ Xt (+b1 row)
    gemm_bf16_kernel<0><<<gridYt, 256, SMEM_BYTES>>>(W1t, Xb, Yt, FD, NN, FD, b1);
    // 4) X = relu(A @ Y2)
    gemm_bf16_kernel<1><<<gridX, 256, SMEM_BYTES>>>(Abf, Yt, Xb, NN, FD, NN, nullptr);
    // 5) Z0t = Wot @ X2t (+bo row)
    gemm_bf16_kernel<0><<<gridZ0, 256, SMEM_BYTES>>>(Wot, Xb, Z0t, CD, NN, FD, bo);

    // 5b) Z0 -> fp8 (iteration-0 input)
    {
        long z8 = (long)CD * NN / 8;
        bf16_to_fp8_kernel<<<(int)((z8 + 255) / 256), 256>>>(Z0t, Zf0, SZ, z8);
    }

    // 6) 10x fp8: Zt = 0.9 * Zt @ At + 0.1 * Z0t
    uint8_t* zin8 = Zf0;
    uint8_t* zout8 = Zfa;
    for (int it = 0; it < 10; it++) {
        gemm_fp8_pow<<<gridZ, 256, F8_SMEM>>>(zin8, Af8, Za, zout8, Z0t, NN, NN);
        zin8 = zout8;
        zout8 = (zin8 == Zfa) ? Zfb : Zfa;
    }

    // 7) column softmax -> [8192, 256] fp32
    softmax_T_kernel<<<NN / 64, 64>>>(Za, (float*)d_out);
}

// round 11
// speedup vs baseline: 1.5597x; 1.5597x over previous
#include <cuda_runtime.h>
#include <cuda_bf16.h>
#include <cstdint>

// ---------------------------------------------------------------------------
// APPNP dense surrogate, N=8192, F=MLP=512, C=256, 10 power iters, alpha=0.1.
// sm_103 (non-'a'): legacy mma.sync bf16 only (tcgen05/fp8-rate unavailable).
// v3 GEMM: BM=64 BN=128 BK=64, 3-stage cp.async, ldmatrix fragments,
// __launch_bounds__(256,2) -> 2 CTAs/SM (4 warps/SMSP) to kill latency stalls.
// Transposed-activation layout: every GEMM's B operand is K-major [N,K].
// ---------------------------------------------------------------------------

#define NN   8192
#define FD   512
#define CD   256
#define ALPHA 0.1f

#define BMr 64
#define BNr 128
#define BKr 64
#define STRB 144                         // smem row stride bytes (72 bf16)
#define A_TILE_B (BMr * STRB)            // 9216
#define B_TILE_B (BNr * STRB)            // 18432
#define STG_B    (A_TILE_B + B_TILE_B)   // 27648
#define NSTG 3
#define SMEM_TOT (NSTG * STG_B)          // 82944 -> 2 CTAs/SM (166KB < 227KB)

// ---- scratch ---------------------------------------------------------------
__device__ __nv_bfloat16 g_Abf[(size_t)NN * NN];     // 128 MB
__device__ __nv_bfloat16 g_Fbf[(size_t)NN * FD];
__device__ __nv_bfloat16 g_W0t[FD * FD];
__device__ __nv_bfloat16 g_W1t[FD * FD];
__device__ __nv_bfloat16 g_Wot[FD * CD];
__device__ __nv_bfloat16 g_Yt[(size_t)FD * NN];
__device__ __nv_bfloat16 g_X[(size_t)NN * FD];
__device__ __nv_bfloat16 g_Z0t[(size_t)CD * NN];
__device__ __nv_bfloat16 g_Za[(size_t)CD * NN];
__device__ __nv_bfloat16 g_Zb[(size_t)CD * NN];

__device__ __forceinline__ uint32_t sptr(const void* p) {
    return (uint32_t)__cvta_generic_to_shared(p);
}
__device__ __forceinline__ void ldsm4(uint32_t a, uint32_t* r) {
    asm volatile("ldmatrix.sync.aligned.m8n8.x4.shared.b16 {%0,%1,%2,%3}, [%4];"
                 : "=r"(r[0]), "=r"(r[1]), "=r"(r[2]), "=r"(r[3]) : "r"(a));
}

// ---- converts --------------------------------------------------------------
__global__ void f32_to_bf16_kernel(const float* __restrict__ src,
                                   __nv_bfloat16* __restrict__ dst, long n8) {
    long t = (long)blockIdx.x * blockDim.x + threadIdx.x;
    if (t >= n8) return;
    long i = t * 8;
    float4 a = *(const float4*)(src + i);
    float4 b = *(const float4*)(src + i + 4);
    union { int4 v; __nv_bfloat16 h[8]; } u;
    u.h[0] = __float2bfloat16(a.x); u.h[1] = __float2bfloat16(a.y);
    u.h[2] = __float2bfloat16(a.z); u.h[3] = __float2bfloat16(a.w);
    u.h[4] = __float2bfloat16(b.x); u.h[5] = __float2bfloat16(b.y);
    u.h[6] = __float2bfloat16(b.z); u.h[7] = __float2bfloat16(b.w);
    *(int4*)(dst + i) = u.v;
}

__global__ void wcvt_T_kernel(const float* __restrict__ W0,
                              const float* __restrict__ W1,
                              const float* __restrict__ Wo,
                              __nv_bfloat16* __restrict__ W0t,
                              __nv_bfloat16* __restrict__ W1t,
                              __nv_bfloat16* __restrict__ Wot) {
    __shared__ float t[32][33];
    const float* src; __nv_bfloat16* dst; int C;
    if (blockIdx.z == 0)      { src = W0; dst = W0t; C = FD; }
    else if (blockIdx.z == 1) { src = W1; dst = W1t; C = FD; }
    else                      { src = Wo; dst = Wot; C = CD; }
    int c0 = blockIdx.x * 32, r0 = blockIdx.y * 32;
    if (c0 >= C) return;
    int tx = threadIdx.x, ty = threadIdx.y;   // (32, 8)
#pragma unroll
    for (int j = 0; j < 32; j += 8)
        t[ty + j][tx] = src[(size_t)(r0 + ty + j) * C + c0 + tx];
    __syncthreads();
#pragma unroll
    for (int j = 0; j < 32; j += 8)
        dst[(size_t)(c0 + ty + j) * FD + r0 + tx] = __float2bfloat16(t[tx][ty + j]);
}

// ---- v3 bf16 GEMM: C[M,N] = epi(Aop[M,K] @ B), B given as Bt[N,K] ---------
// MODE 0: acc + bias[row]   MODE 1: relu(acc)   MODE 2: 0.9*acc + 0.1*Z0[r,c]
// 8 warps, warp tile 32x32 (mi=2 m16 tiles, nj=4 n8 tiles).
template <int MODE>
__global__ void __launch_bounds__(256, 2)
gemm_v3(const __nv_bfloat16* __restrict__ Aop,
        const __nv_bfloat16* __restrict__ Btp,
        __nv_bfloat16* __restrict__ Cmat,
        int M, int N, int K,
        const float* __restrict__ bias,
        const __nv_bfloat16* __restrict__ Z0) {
    extern __shared__ char sm[];
    const uint32_t base = sptr(sm);

    const int tid  = threadIdx.x;
    const int lane = tid & 31;
    const int warp = tid >> 5;
    const int wm = (warp & 1) * 32;
    const int wn = (warp >> 1) * 32;
    const int bm0 = blockIdx.y * BMr;
    const int bn0 = blockIdx.x * BNr;
    const int nIter = K / BKr;

    auto load_stage = [&](int st, int kiter) {
        const int k0 = kiter * BKr;
        const uint32_t sa = base + st * STG_B;
        const uint32_t sb = sa + A_TILE_B;
#pragma unroll
        for (int i = 0; i < 2; i++) {         // A: 64 rows x 8 16B-chunks
            int id = tid + i * 256, row = id >> 3, c = id & 7;
            const void* g = Aop + (size_t)(bm0 + row) * K + k0 + c * 8;
            asm volatile("cp.async.cg.shared.global [%0], [%1], 16;\n"
                         :: "r"(sa + row * STRB + c * 16), "l"(g));
        }
#pragma unroll
        for (int i = 0; i < 4; i++) {         // B: 128 rows x 8 chunks
            int id = tid + i * 256, row = id >> 3, c = id & 7;
            const void* g = Btp + (size_t)(bn0 + row) * K + k0 + c * 8;
            asm volatile("cp.async.cg.shared.global [%0], [%1], 16;\n"
                         :: "r"(sb + row * STRB + c * 16), "l"(g));
        }
        asm volatile("cp.async.commit_group;\n");
    };

    // ldmatrix lane addressing: tile = lane>>3 -> (row +8 if bit0, col +8 if bit1)
    const int lrow   = (lane & 7) + ((lane >> 3) & 1) * 8;
    const int lcol16 = (lane >> 4) * 16;             // byte offset (+8 elems)
    const uint32_t aoff = (uint32_t)(wm + lrow) * STRB + lcol16;
    const uint32_t boff = (uint32_t)(wn + lrow) * STRB + lcol16;

    float acc[2][4][4];
#pragma unroll
    for (int i = 0; i < 2; i++)
#pragma unroll
        for (int j = 0; j < 4; j++)
#pragma unroll
            for (int k = 0; k < 4; k++) acc[i][j][k] = 0.f;

    load_stage(0, 0);
    load_stage(1, 1);

    for (int it = 0; it < nIter; it++) {
        asm volatile("cp.async.wait_group %0;\n" :: "n"(NSTG - 2));
        __syncthreads();

        int nxt = it + NSTG - 1;
        if (nxt < nIter) load_stage(nxt % NSTG, nxt);
        else asm volatile("cp.async.commit_group;\n");

        const uint32_t sa = base + (it % NSTG) * STG_B;
        const uint32_t sb = sa + A_TILE_B;

#pragma unroll
        for (int kk = 0; kk < BKr; kk += 16) {
            uint32_t af[2][4], bf[2][4];
#pragma unroll
            for (int mi = 0; mi < 2; mi++)
                ldsm4(sa + aoff + mi * 16 * STRB + kk * 2, af[mi]);
#pragma unroll
            for (int nb = 0; nb < 2; nb++)
                ldsm4(sb + boff + nb * 16 * STRB + kk * 2, bf[nb]);
            // bf[nb]: r0=b0(nj=2nb) r1=b0(nj=2nb+1) r2=b1(nj=2nb) r3=b1(nj=2nb+1)
#pragma unroll
            for (int mi = 0; mi < 2; mi++)
#pragma unroll
                for (int nj = 0; nj < 4; nj++) {
                    uint32_t b0 = bf[nj >> 1][nj & 1];
                    uint32_t b1 = bf[nj >> 1][2 + (nj & 1)];
                    asm volatile(
                        "mma.sync.aligned.m16n8k16.row.col.f32.bf16.bf16.f32 "
                        "{%0,%1,%2,%3}, {%4,%5,%6,%7}, {%8,%9}, {%0,%1,%2,%3};\n"
                        : "+f"(acc[mi][nj][0]), "+f"(acc[mi][nj][1]),
                          "+f"(acc[mi][nj][2]), "+f"(acc[mi][nj][3])
                        : "r"(af[mi][0]), "r"(af[mi][1]), "r"(af[mi][2]), "r"(af[mi][3]),
                          "r"(b0), "r"(b1));
                }
        }
    }

    // --- epilogue ---
#pragma unroll
    for (int mi = 0; mi < 2; mi++) {
#pragma unroll
        for (int nj = 0; nj < 4; nj++) {
            int row0 = bm0 + wm + mi * 16 + (lane >> 2);
            int col  = bn0 + wn + nj * 8 + (lane & 3) * 2;
#pragma unroll
            for (int h = 0; h < 2; h++) {
                int row = row0 + h * 8;
                float v0 = acc[mi][nj][2 * h + 0];
                float v1 = acc[mi][nj][2 * h + 1];
                if (MODE == 0) { float b = bias[row]; v0 += b; v1 += b; }
                if (MODE == 1) { v0 = fmaxf(v0, 0.f); v1 = fmaxf(v1, 0.f); }
                if (MODE == 2) {
                    __nv_bfloat162 z = *(const __nv_bfloat162*)(Z0 + (size_t)row * N + col);
                    v0 = (1.f - ALPHA) * v0 + ALPHA * __bfloat162float(z.x);
                    v1 = (1.f - ALPHA) * v1 + ALPHA * __bfloat162float(z.y);
                }
                *(__nv_bfloat162*)(Cmat + (size_t)row * N + col) = __floats2bfloat162_rn(v0, v1);
            }
        }
    }
}

// ---- column softmax of Zt[256, 8192] -> out[8192, 256] fp32 ---------------
__global__ void softmax_T_kernel(const __nv_bfloat16* __restrict__ Zt,
                                 float* __restrict__ out) {
    __shared__ float tile[2][32][33];
    int warp = threadIdx.x >> 5, lane = threadIdx.x & 31;
    int n0 = blockIdx.x * 64 + warp * 32;
    int n = n0 + lane;

    float mx = -1e30f;
#pragma unroll 8
    for (int c = 0; c < CD; c++)
        mx = fmaxf(mx, __bfloat162float(Zt[(size_t)c * NN + n]));
    float s = 0.f;
#pragma unroll 8
    for (int c = 0; c < CD; c++)
        s += __expf(__bfloat162float(Zt[(size_t)c * NN + n]) - mx);
    float inv = 1.f / s;

    for (int c0 = 0; c0 < CD; c0 += 32) {
#pragma unroll
        for (int cc = 0; cc < 32; cc++)
            tile[warp][cc][lane] =
                __expf(__bfloat162float(Zt[(size_t)(c0 + cc) * NN + n]) - mx) * inv;
        __syncwarp();
#pragma unroll
        for (int i = 0; i < 32; i++)
            out[(size_t)(n0 + i) * CD + c0 + lane] = tile[warp][lane][i];
        __syncwarp();
    }
}

// ---------------------------------------------------------------------------
extern "C" void kernel_launch(void* const* d_in, const int* in_sizes, int n_in,
                              void* d_out, int out_size) {
    const float* features = (const float*)d_in[0];
    const float* fltr     = (const float*)d_in[1];
    const float* W0       = (const float*)d_in[2];
    const float* b0       = (const float*)d_in[3];
    const float* W1       = (const float*)d_in[4];
    const float* b1       = (const float*)d_in[5];
    const float* Wo       = (const float*)d_in[6];
    const float* bo       = (const float*)d_in[7];

    void *pA, *pF, *pW0, *pW1, *pWo, *pYt, *pX, *pZ0, *pZa, *pZb;
    cudaGetSymbolAddress(&pA,  g_Abf);
    cudaGetSymbolAddress(&pF,  g_Fbf);
    cudaGetSymbolAddress(&pW0, g_W0t);
    cudaGetSymbolAddress(&pW1, g_W1t);
    cudaGetSymbolAddress(&pWo, g_Wot);
    cudaGetSymbolAddress(&pYt, g_Yt);
    cudaGetSymbolAddress(&pX,  g_X);
    cudaGetSymbolAddress(&pZ0, g_Z0t);
    cudaGetSymbolAddress(&pZa, g_Za);
    cudaGetSymbolAddress(&pZb, g_Zb);

    __nv_bfloat16* Abf = (__nv_bfloat16*)pA;
    __nv_bfloat16* Fbf = (__nv_bfloat16*)pF;
    __nv_bfloat16* W0t = (__nv_bfloat16*)pW0;
    __nv_bfloat16* W1t = (__nv_bfloat16*)pW1;
    __nv_bfloat16* Wot = (__nv_bfloat16*)pWo;
    __nv_bfloat16* Yt  = (__nv_bfloat16*)pYt;
    __nv_bfloat16* Xb  = (__nv_bfloat16*)pX;
    __nv_bfloat16* Z0t = (__nv_bfloat16*)pZ0;
    __nv_bfloat16* Za  = (__nv_bfloat16*)pZa;
    __nv_bfloat16* Zb  = (__nv_bfloat16*)pZb;

    cudaFuncSetAttribute(gemm_v3<0>, cudaFuncAttributeMaxDynamicSharedMemorySize, SMEM_TOT);
    cudaFuncSetAttribute(gemm_v3<1>, cudaFuncAttributeMaxDynamicSharedMemorySize, SMEM_TOT);
    cudaFuncSetAttribute(gemm_v3<2>, cudaFuncAttributeMaxDynamicSharedMemorySize, SMEM_TOT);

    // 0) converts
    {
        long n8 = (long)NN * NN / 8;
        f32_to_bf16_kernel<<<(int)((n8 + 255) / 256), 256>>>(fltr, Abf, n8);
        long f8 = (long)NN * FD / 8;
        f32_to_bf16_kernel<<<(int)((f8 + 255) / 256), 256>>>(features, Fbf, f8);
        wcvt_T_kernel<<<dim3(16, 16, 3), dim3(32, 8)>>>(W0, W1, Wo, W0t, W1t, Wot);
    }

    dim3 gridYt(NN / BNr, FD / BMr);   // (64, 8)  = 512 CTAs  [512,8192]
    dim3 gridX (FD / BNr, NN / BMr);   // (4, 128) = 512 CTAs  [8192,512]
    dim3 gridZ (NN / BNr, CD / BMr);   // (64, 4)  = 256 CTAs  [256,8192]

    // 1) Yt = W0t @ Ft (+b0 row)
    gemm_v3<0><<<gridYt, 256, SMEM_TOT>>>(W0t, Fbf, Yt, FD, NN, FD, b0, nullptr);
    // 2) X = relu(A @ Y)   (Bt = Yt)
    gemm_v3<1><<<gridX, 256, SMEM_TOT>>>(Abf, Yt, Xb, NN, FD, NN, nullptr, nullptr);
    // 3) Yt = W1t @ Xt (+b1 row)
    gemm_v3<0><<<gridYt, 256, SMEM_TOT>>>(W1t, Xb, Yt, FD, NN, FD, b1, nullptr);
    // 4) X = relu(A @ Y2)
    gemm_v3<1><<<gridX, 256, SMEM_TOT>>>(Abf, Yt, Xb, NN, FD, NN, nullptr, nullptr);
    // 5) Z0t = Wot @ X2t (+bo row)
    gemm_v3<0><<<gridZ, 256, SMEM_TOT>>>(Wot, Xb, Z0t, CD, NN, FD, bo, nullptr);

    // 6) 10x: Zt = 0.9 * Zt @ At + 0.1 * Z0t   (Bt = A natural)
    __nv_bfloat16* zin = Z0t;
    __nv_bfloat16* zout = Za;
    for (int it = 0; it < 10; it++) {
        gemm_v3<2><<<gridZ, 256, SMEM_TOT>>>(zin, Abf, zout, CD, NN, NN, nullptr, Z0t);
        zin = zout;
        zout = (zin == Za) ? Zb : Za;
    }

    // 7) column softmax -> [8192, 256] fp32
    softmax_T_kernel<<<NN / 64, 64>>>(zin, (float*)d_out);
}

// round 12
// speedup vs baseline: 1.6332x; 1.0471x over previous
#include <cuda_runtime.h>
#include <cuda_bf16.h>
#include <cstdint>

// ---------------------------------------------------------------------------
// APPNP dense surrogate, N=8192, F=MLP=512, C=256, 10 power iters, alpha=0.1.
// sm_103 (non-'a'): legacy mma.sync bf16 only (tcgen05/fp8-rate unavailable).
// v4 GEMM: BM=64 BN=128 BK=64, 4-stage cp.async (prefetch distance 3 iters to
// cover ~600cyc DRAM latency), ldmatrix fragments, __launch_bounds__(256,2)
// -> 2 CTAs/SM. Transposed-activation layout: B operand always K-major [N,K].
// ---------------------------------------------------------------------------

#define NN   8192
#define FD   512
#define CD   256
#define ALPHA 0.1f

#define BMr 64
#define BNr 128
#define BKr 64
#define STRB 144                         // smem row stride bytes (72 bf16)
#define A_TILE_B (BMr * STRB)            // 9216
#define B_TILE_B (BNr * STRB)            // 18432
#define STG_B    (A_TILE_B + B_TILE_B)   // 27648
#define NSTG 4
#define SMEM_TOT (NSTG * STG_B)          // 110592 -> 2 CTAs/SM (221KB < 228KB)

// ---- scratch ---------------------------------------------------------------
__device__ __nv_bfloat16 g_Abf[(size_t)NN * NN];     // 128 MB
__device__ __nv_bfloat16 g_Fbf[(size_t)NN * FD];
__device__ __nv_bfloat16 g_W0t[FD * FD];
__device__ __nv_bfloat16 g_W1t[FD * FD];
__device__ __nv_bfloat16 g_Wot[FD * CD];
__device__ __nv_bfloat16 g_Yt[(size_t)FD * NN];
__device__ __nv_bfloat16 g_X[(size_t)NN * FD];
__device__ __nv_bfloat16 g_Z0t[(size_t)CD * NN];
__device__ __nv_bfloat16 g_Za[(size_t)CD * NN];
__device__ __nv_bfloat16 g_Zb[(size_t)CD * NN];

__device__ __forceinline__ uint32_t sptr(const void* p) {
    return (uint32_t)__cvta_generic_to_shared(p);
}
__device__ __forceinline__ void ldsm4(uint32_t a, uint32_t* r) {
    asm volatile("ldmatrix.sync.aligned.m8n8.x4.shared.b16 {%0,%1,%2,%3}, [%4];"
                 : "=r"(r[0]), "=r"(r[1]), "=r"(r[2]), "=r"(r[3]) : "r"(a));
}

// ---- converts --------------------------------------------------------------
__global__ void f32_to_bf16_kernel(const float* __restrict__ src,
                                   __nv_bfloat16* __restrict__ dst, long n8) {
    long t = (long)blockIdx.x * blockDim.x + threadIdx.x;
    if (t >= n8) return;
    long i = t * 8;
    float4 a = *(const float4*)(src + i);
    float4 b = *(const float4*)(src + i + 4);
    union { int4 v; __nv_bfloat16 h[8]; } u;
    u.h[0] = __float2bfloat16(a.x); u.h[1] = __float2bfloat16(a.y);
    u.h[2] = __float2bfloat16(a.z); u.h[3] = __float2bfloat16(a.w);
    u.h[4] = __float2bfloat16(b.x); u.h[5] = __float2bfloat16(b.y);
    u.h[6] = __float2bfloat16(b.z); u.h[7] = __float2bfloat16(b.w);
    *(int4*)(dst + i) = u.v;
}

__global__ void wcvt_T_kernel(const float* __restrict__ W0,
                              const float* __restrict__ W1,
                              const float* __restrict__ Wo,
                              __nv_bfloat16* __restrict__ W0t,
                              __nv_bfloat16* __restrict__ W1t,
                              __nv_bfloat16* __restrict__ Wot) {
    __shared__ float t[32][33];
    const float* src; __nv_bfloat16* dst; int C;
    if (blockIdx.z == 0)      { src = W0; dst = W0t; C = FD; }
    else if (blockIdx.z == 1) { src = W1; dst = W1t; C = FD; }
    else                      { src = Wo; dst = Wot; C = CD; }
    int c0 = blockIdx.x * 32, r0 = blockIdx.y * 32;
    if (c0 >= C) return;
    int tx = threadIdx.x, ty = threadIdx.y;   // (32, 8)
#pragma unroll
    for (int j = 0; j < 32; j += 8)
        t[ty + j][tx] = src[(size_t)(r0 + ty + j) * C + c0 + tx];
    __syncthreads();
#pragma unroll
    for (int j = 0; j < 32; j += 8)
        dst[(size_t)(c0 + ty + j) * FD + r0 + tx] = __float2bfloat16(t[tx][ty + j]);
}

// ---- v4 bf16 GEMM: C[M,N] = epi(Aop[M,K] @ B), B given as Bt[N,K] ---------
// MODE 0: acc + bias[row]   MODE 1: relu(acc)   MODE 2: 0.9*acc + 0.1*Z0[r,c]
// 8 warps, warp tile 32x32 (mi=2 m16 tiles, nj=4 n8 tiles).
template <int MODE>
__global__ void __launch_bounds__(256, 2)
gemm_v4(const __nv_bfloat16* __restrict__ Aop,
        const __nv_bfloat16* __restrict__ Btp,
        __nv_bfloat16* __restrict__ Cmat,
        int M, int N, int K,
        const float* __restrict__ bias,
        const __nv_bfloat16* __restrict__ Z0) {
    extern __shared__ char sm[];
    const uint32_t base = sptr(sm);

    const int tid  = threadIdx.x;
    const int lane = tid & 31;
    const int warp = tid >> 5;
    const int wm = (warp & 1) * 32;
    const int wn = (warp >> 1) * 32;
    const int bm0 = blockIdx.y * BMr;
    const int bn0 = blockIdx.x * BNr;
    const int nIter = K / BKr;

    auto load_stage = [&](int st, int kiter) {
        const int k0 = kiter * BKr;
        const uint32_t sa = base + st * STG_B;
        const uint32_t sb = sa + A_TILE_B;
#pragma unroll
        for (int i = 0; i < 2; i++) {         // A: 64 rows x 8 16B-chunks
            int id = tid + i * 256, row = id >> 3, c = id & 7;
            const void* g = Aop + (size_t)(bm0 + row) * K + k0 + c * 8;
            asm volatile("cp.async.cg.shared.global [%0], [%1], 16;\n"
                         :: "r"(sa + row * STRB + c * 16), "l"(g));
        }
#pragma unroll
        for (int i = 0; i < 4; i++) {         // B: 128 rows x 8 chunks
            int id = tid + i * 256, row = id >> 3, c = id & 7;
            const void* g = Btp + (size_t)(bn0 + row) * K + k0 + c * 8;
            asm volatile("cp.async.cg.shared.global [%0], [%1], 16;\n"
                         :: "r"(sb + row * STRB + c * 16), "l"(g));
        }
        asm volatile("cp.async.commit_group;\n");
    };

    // ldmatrix lane addressing: tile = lane>>3 -> (row +8 if bit0, col +8 if bit1)
    const int lrow   = (lane & 7) + ((lane >> 3) & 1) * 8;
    const int lcol16 = (lane >> 4) * 16;             // byte offset (+8 elems)
    const uint32_t aoff = (uint32_t)(wm + lrow) * STRB + lcol16;
    const uint32_t boff = (uint32_t)(wn + lrow) * STRB + lcol16;

    float acc[2][4][4];
#pragma unroll
    for (int i = 0; i < 2; i++)
#pragma unroll
        for (int j = 0; j < 4; j++)
#pragma unroll
            for (int k = 0; k < 4; k++) acc[i][j][k] = 0.f;

    // prologue: fill NSTG-1 = 3 stages
    load_stage(0, 0);
    load_stage(1, 1);
    load_stage(2, 2);

    for (int it = 0; it < nIter; it++) {
        asm volatile("cp.async.wait_group %0;\n" :: "n"(NSTG - 2));
        __syncthreads();

        int nxt = it + NSTG - 1;
        if (nxt < nIter) load_stage(nxt % NSTG, nxt);
        else asm volatile("cp.async.commit_group;\n");

        const uint32_t sa = base + (it % NSTG) * STG_B;
        const uint32_t sb = sa + A_TILE_B;

#pragma unroll
        for (int kk = 0; kk < BKr; kk += 16) {
            uint32_t af[2][4], bf[2][4];
#pragma unroll
            for (int mi = 0; mi < 2; mi++)
                ldsm4(sa + aoff + mi * 16 * STRB + kk * 2, af[mi]);
#pragma unroll
            for (int nb = 0; nb < 2; nb++)
                ldsm4(sb + boff + nb * 16 * STRB + kk * 2, bf[nb]);
            // bf[nb]: r0=b0(nj=2nb) r1=b0(nj=2nb+1) r2=b1(nj=2nb) r3=b1(nj=2nb+1)
#pragma unroll
            for (int mi = 0; mi < 2; mi++)
#pragma unroll
                for (int nj = 0; nj < 4; nj++) {
                    uint32_t b0 = bf[nj >> 1][nj & 1];
                    uint32_t b1 = bf[nj >> 1][2 + (nj & 1)];
                    asm volatile(
                        "mma.sync.aligned.m16n8k16.row.col.f32.bf16.bf16.f32 "
                        "{%0,%1,%2,%3}, {%4,%5,%6,%7}, {%8,%9}, {%0,%1,%2,%3};\n"
                        : "+f"(acc[mi][nj][0]), "+f"(acc[mi][nj][1]),
                          "+f"(acc[mi][nj][2]), "+f"(acc[mi][nj][3])
                        : "r"(af[mi][0]), "r"(af[mi][1]), "r"(af[mi][2]), "r"(af[mi][3]),
                          "r"(b0), "r"(b1));
                }
        }
    }

    // --- epilogue ---
#pragma unroll
    for (int mi = 0; mi < 2; mi++) {
#pragma unroll
        for (int nj = 0; nj < 4; nj++) {
            int row0 = bm0 + wm + mi * 16 + (lane >> 2);
            int col  = bn0 + wn + nj * 8 + (lane & 3) * 2;
#pragma unroll
            for (int h = 0; h < 2; h++) {
                int row = row0 + h * 8;
                float v0 = acc[mi][nj][2 * h + 0];
                float v1 = acc[mi][nj][2 * h + 1];
                if (MODE == 0) { float b = bias[row]; v0 += b; v1 += b; }
                if (MODE == 1) { v0 = fmaxf(v0, 0.f); v1 = fmaxf(v1, 0.f); }
                if (MODE == 2) {
                    __nv_bfloat162 z = *(const __nv_bfloat162*)(Z0 + (size_t)row * N + col);
                    v0 = (1.f - ALPHA) * v0 + ALPHA * __bfloat162float(z.x);
                    v1 = (1.f - ALPHA) * v1 + ALPHA * __bfloat162float(z.y);
                }
                *(__nv_bfloat162*)(Cmat + (size_t)row * N + col) = __floats2bfloat162_rn(v0, v1);
            }
        }
    }
}

// ---- column softmax of Zt[256, 8192] -> out[8192, 256] fp32 ---------------
__global__ void softmax_T_kernel(const __nv_bfloat16* __restrict__ Zt,
                                 float* __restrict__ out) {
    __shared__ float tile[2][32][33];
    int warp = threadIdx.x >> 5, lane = threadIdx.x & 31;
    int n0 = blockIdx.x * 64 + warp * 32;
    int n = n0 + lane;

    float mx = -1e30f;
#pragma unroll 8
    for (int c = 0; c < CD; c++)
        mx = fmaxf(mx, __bfloat162float(Zt[(size_t)c * NN + n]));
    float s = 0.f;
#pragma unroll 8
    for (int c = 0; c < CD; c++)
        s += __expf(__bfloat162float(Zt[(size_t)c * NN + n]) - mx);
    float inv = 1.f / s;

    for (int c0 = 0; c0 < CD; c0 += 32) {
#pragma unroll
        for (int cc = 0; cc < 32; cc++)
            tile[warp][cc][lane] =
                __expf(__bfloat162float(Zt[(size_t)(c0 + cc) * NN + n]) - mx) * inv;
        __syncwarp();
#pragma unroll
        for (int i = 0; i < 32; i++)
            out[(size_t)(n0 + i) * CD + c0 + lane] = tile[warp][lane][i];
        __syncwarp();
    }
}

// ---------------------------------------------------------------------------
extern "C" void kernel_launch(void* const* d_in, const int* in_sizes, int n_in,
                              void* d_out, int out_size) {
    const float* features = (const float*)d_in[0];
    const float* fltr     = (const float*)d_in[1];
    const float* W0       = (const float*)d_in[2];
    const float* b0       = (const float*)d_in[3];
    const float* W1       = (const float*)d_in[4];
    const float* b1       = (const float*)d_in[5];
    const float* Wo       = (const float*)d_in[6];
    const float* bo       = (const float*)d_in[7];

    void *pA, *pF, *pW0, *pW1, *pWo, *pYt, *pX, *pZ0, *pZa, *pZb;
    cudaGetSymbolAddress(&pA,  g_Abf);
    cudaGetSymbolAddress(&pF,  g_Fbf);
    cudaGetSymbolAddress(&pW0, g_W0t);
    cudaGetSymbolAddress(&pW1, g_W1t);
    cudaGetSymbolAddress(&pWo, g_Wot);
    cudaGetSymbolAddress(&pYt, g_Yt);
    cudaGetSymbolAddress(&pX,  g_X);
    cudaGetSymbolAddress(&pZ0, g_Z0t);
    cudaGetSymbolAddress(&pZa, g_Za);
    cudaGetSymbolAddress(&pZb, g_Zb);

    __nv_bfloat16* Abf = (__nv_bfloat16*)pA;
    __nv_bfloat16* Fbf = (__nv_bfloat16*)pF;
    __nv_bfloat16* W0t = (__nv_bfloat16*)pW0;
    __nv_bfloat16* W1t = (__nv_bfloat16*)pW1;
    __nv_bfloat16* Wot = (__nv_bfloat16*)pWo;
    __nv_bfloat16* Yt  = (__nv_bfloat16*)pYt;
    __nv_bfloat16* Xb  = (__nv_bfloat16*)pX;
    __nv_bfloat16* Z0t = (__nv_bfloat16*)pZ0;
    __nv_bfloat16* Za  = (__nv_bfloat16*)pZa;
    __nv_bfloat16* Zb  = (__nv_bfloat16*)pZb;

    cudaFuncSetAttribute(gemm_v4<0>, cudaFuncAttributeMaxDynamicSharedMemorySize, SMEM_TOT);
    cudaFuncSetAttribute(gemm_v4<1>, cudaFuncAttributeMaxDynamicSharedMemorySize, SMEM_TOT);
    cudaFuncSetAttribute(gemm_v4<2>, cudaFuncAttributeMaxDynamicSharedMemorySize, SMEM_TOT);

    // 0) converts
    {
        long n8 = (long)NN * NN / 8;
        f32_to_bf16_kernel<<<(int)((n8 + 255) / 256), 256>>>(fltr, Abf, n8);
        long f8 = (long)NN * FD / 8;
        f32_to_bf16_kernel<<<(int)((f8 + 255) / 256), 256>>>(features, Fbf, f8);
        wcvt_T_kernel<<<dim3(16, 16, 3), dim3(32, 8)>>>(W0, W1, Wo, W0t, W1t, Wot);
    }

    dim3 gridYt(NN / BNr, FD / BMr);   // (64, 8)  = 512 CTAs  [512,8192]
    dim3 gridX (FD / BNr, NN / BMr);   // (4, 128) = 512 CTAs  [8192,512]
    dim3 gridZ (NN / BNr, CD / BMr);   // (64, 4)  = 256 CTAs  [256,8192]

    // 1) Yt = W0t @ Ft (+b0 row)
    gemm_v4<0><<<gridYt, 256, SMEM_TOT>>>(W0t, Fbf, Yt, FD, NN, FD, b0, nullptr);
    // 2) X = relu(A @ Y)   (Bt = Yt)
    gemm_v4<1><<<gridX, 256, SMEM_TOT>>>(Abf, Yt, Xb, NN, FD, NN, nullptr, nullptr);
    // 3) Yt = W1t @ Xt (+b1 row)
    gemm_v4<0><<<gridYt, 256, SMEM_TOT>>>(W1t, Xb, Yt, FD, NN, FD, b1, nullptr);
    // 4) X = relu(A @ Y2)
    gemm_v4<1><<<gridX, 256, SMEM_TOT>>>(Abf, Yt, Xb, NN, FD, NN, nullptr, nullptr);
    // 5) Z0t = Wot @ X2t (+bo row)
    gemm_v4<0><<<gridZ, 256, SMEM_TOT>>>(Wot, Xb, Z0t, CD, NN, FD, bo, nullptr);

    // 6) 10x: Zt = 0.9 * Zt @ At + 0.1 * Z0t   (Bt = A natural)
    __nv_bfloat16* zin = Z0t;
    __nv_bfloat16* zout = Za;
    for (int it = 0; it < 10; it++) {
        gemm_v4<2><<<gridZ, 256, SMEM_TOT>>>(zin, Abf, zout, CD, NN, NN, nullptr, Z0t);
        zin = zout;
        zout = (zin == Za) ? Zb : Za;
    }

    // 7) column softmax -> [8192, 256] fp32
    softmax_T_kernel<<<NN / 64, 64>>>(zin, (float*)d_out);
}